// round 15
// baseline (speedup 1.0000x reference)
#include <cuda_runtime.h>

// OHEM cross-entropy on GB300 — single launch, R6 layout + slimmed epilogue
// (per-warp striped REDG partials, no shared round-trip).
// input (16,19,512,512) f32, target (16,512,512) i32, out: scalar f32.
#define CCH    19
#define HW     262144          // 512*512 = 2^18
#define BATCH  16
#define BHW    (BATCH*HW)      // 4,194,304
#define NMIN   262144
#define THRESH 0.35667494f     // -log(0.7)
#define NBINS  65536
#define NPART  128

#define BLK       256
#define CE_BLOCKS (BHW / BLK)  // 16384

// Static scratch (no allocs). Slots/ticket self-reset each graph replay.
__device__ double             g_part_sum[NPART];
__device__ unsigned long long g_part_cnt[NPART];
__device__ unsigned int       g_hist_cnt[NBINS];   // last block only, fallback only
__device__ float              g_hist_sum[NBINS];
__device__ unsigned int       g_ticket1 = 0;

// ---------------------------------------------------------------------------
__device__ __forceinline__ float pixel_loss(const float* __restrict__ x, int p, int t) {
    const int b = p >> 18;
    const int s = p & (HW - 1);
    const float* xp = x + (size_t)b * (size_t)(CCH * HW) + (size_t)s;
    float v[CCH];
    #pragma unroll
    for (int c = 0; c < CCH; c++) v[c] = __ldg(xp + (size_t)c * HW);
    float m = v[0];
    #pragma unroll
    for (int c = 1; c < CCH; c++) m = fmaxf(m, v[c]);
    float se = 0.0f, xt = v[0];
    #pragma unroll
    for (int c = 0; c < CCH; c++) {
        se += __expf(v[c] - m);
        if (c == t) xt = v[c];
    }
    return (t == 255) ? 0.0f : (m - xt + __logf(se));
}

// ---------------------------------------------------------------------------
__global__ __launch_bounds__(BLK) void ce_k(const float* __restrict__ x,
                                            const int* __restrict__ tgt,
                                            float* __restrict__ out) {
    const int p = blockIdx.x * BLK + threadIdx.x;   // exact grid: BHW/BLK
    const float loss = pixel_loss(x, p, __ldg(tgt + p));

    // Warp reduction of thresholded count/sum; lane 0 posts striped partials.
    const bool   gt = loss > THRESH;
    float        sv = gt ? loss : 0.0f;
    unsigned int cv = gt ? 1u : 0u;
    #pragma unroll
    for (int o = 16; o > 0; o >>= 1) {
        sv += __shfl_down_sync(0xffffffffu, sv, o);
        cv += __shfl_down_sync(0xffffffffu, cv, o);
    }
    const int lane = threadIdx.x & 31, w = threadIdx.x >> 5;
    if (lane == 0) {
        const int slot = (blockIdx.x * 8 + w) & (NPART - 1);
        atomicAdd(&g_part_sum[slot], (double)sv);            // REDG, no return
        atomicAdd(&g_part_cnt[slot], (unsigned long long)cv);
    }
    __syncthreads();
    __shared__ bool isLast;
    if (threadIdx.x == 0) {
        __threadfence();   // cumulative over the CTA barrier: all warps' REDGs visible
        const unsigned ret = atomicAdd(&g_ticket1, 1u);
        isLast = (ret == (unsigned)(gridDim.x - 1));
    }
    __syncthreads();
    if (!isLast) return;

    // ======================= LAST BLOCK ONLY ===============================
    const int tt = threadIdx.x;
    double             ds = (tt < NPART) ? g_part_sum[tt] : 0.0;
    unsigned long long dc = (tt < NPART) ? g_part_cnt[tt] : 0ull;
    if (tt < NPART) { g_part_sum[tt] = 0.0; g_part_cnt[tt] = 0ull; }  // self-reset

    __shared__ double             fs[BLK];
    __shared__ unsigned long long fc[BLK];
    fs[tt] = ds; fc[tt] = dc;
    __syncthreads();
    for (int o = BLK / 2; o > 0; o >>= 1) {
        if (tt < o) { fs[tt] += fs[tt + o]; fc[tt] += fc[tt + o]; }
        __syncthreads();
    }
    __shared__ int fastpath;
    if (tt == 0) {
        const double             S = fs[0];
        const unsigned long long C = fc[0];
        if (C > (unsigned long long)NMIN) { out[0] = (float)(S / (double)C); fastpath = 1; }
        else                              { fastpath = 0; }
        g_ticket1 = 0u;                          // self-reset for next replay
    }
    __syncthreads();
    if (fastpath) return;                        // <-- bench data exits here

    // ---- Fallback (top-NMIN mean). Single block, correctness-only path. ----
    for (int i = tt; i < NBINS; i += BLK) { g_hist_cnt[i] = 0u; g_hist_sum[i] = 0.0f; }
    __syncthreads();
    for (int q = tt; q < BHW; q += BLK) {
        const float l = pixel_loss(x, q, __ldg(tgt + q));
        unsigned bin = __float_as_uint(l) >> 16;     // monotone for l >= 0
        if (bin >= NBINS) bin = NBINS - 1;
        atomicAdd(&g_hist_cnt[bin], 1u);
        atomicAdd(&g_hist_sum[bin], l);
    }
    __syncthreads();

    // Top-NMIN select over the histogram.
    __shared__ unsigned long long scnt[BLK];
    __shared__ double             ssum[BLK];
    {
        unsigned long long c = 0ull; double s = 0.0;
        for (int j = 0; j < NBINS / BLK; j++) {
            const int bin = NBINS - 1 - (tt * (NBINS / BLK) + j);
            c += g_hist_cnt[bin];
            s += (double)g_hist_sum[bin];
        }
        scnt[tt] = c; ssum[tt] = s;
    }
    __syncthreads();
    if (tt == 0) {
        unsigned long long cum = 0ull; double sum = 0.0;
        int chunk = 0;
        for (chunk = 0; chunk < BLK; chunk++) {
            if (cum + scnt[chunk] >= (unsigned long long)NMIN) break;
            cum += scnt[chunk]; sum += ssum[chunk];
        }
        double result;
        if (chunk == BLK) {
            result = (cum > 0) ? (sum / (double)cum) : 0.0;
        } else {
            for (int j = 0; j < NBINS / BLK; j++) {
                const int bin = NBINS - 1 - (chunk * (NBINS / BLK) + j);
                const unsigned long long bc = g_hist_cnt[bin];
                const double             bs = (double)g_hist_sum[bin];
                if (cum + bc >= (unsigned long long)NMIN) {
                    const unsigned long long rem = (unsigned long long)NMIN - cum;
                    sum += (bc ? bs / (double)bc : 0.0) * (double)rem;
                    break;
                }
                cum += bc; sum += bs;
            }
            result = sum / (double)NMIN;
        }
        out[0] = (float)result;
    }
}

// ---------------------------------------------------------------------------
extern "C" void kernel_launch(void* const* d_in, const int* in_sizes, int n_in,
                              void* d_out, int out_size) {
    const float* x;
    const int*   tg;
    if (in_sizes[0] >= in_sizes[1]) { x = (const float*)d_in[0]; tg = (const int*)d_in[1]; }
    else                            { x = (const float*)d_in[1]; tg = (const int*)d_in[0]; }

    ce_k<<<CE_BLOCKS, BLK>>>(x, tg, (float*)d_out);
}

// round 17
// speedup vs baseline: 1.2569x; 1.2569x over previous
#include <cuda_runtime.h>

// OHEM cross-entropy on GB300 — single launch (R6 structure).
// Change vs R6: ticket uses atom.acq_rel.gpu instead of __threadfence()+atomicAdd,
// eliminating the per-block CCTL.IVALL (L1D invalidate) and MEMBAR.
// input (16,19,512,512) f32, target (16,512,512) i32, out: scalar f32.
#define CCH    19
#define HW     262144          // 512*512 = 2^18
#define BATCH  16
#define BHW    (BATCH*HW)      // 4,194,304
#define NMIN   262144
#define THRESH 0.35667494f     // -log(0.7)
#define NBINS  65536
#define NPART  64

#define BLK       256
#define CE_BLOCKS (BHW / BLK)  // 16384

// Static scratch (no allocs). Slots/ticket self-reset each graph replay.
__device__ double             g_part_sum[NPART];
__device__ unsigned long long g_part_cnt[NPART];
__device__ unsigned int       g_hist_cnt[NBINS];   // last block only, fallback only
__device__ float              g_hist_sum[NBINS];
__device__ unsigned int       g_ticket1 = 0;

// ---------------------------------------------------------------------------
__device__ __forceinline__ float pixel_loss(const float* __restrict__ x, int p, int t) {
    const int b = p >> 18;
    const int s = p & (HW - 1);
    const float* xp = x + (size_t)b * (size_t)(CCH * HW) + (size_t)s;
    float v[CCH];
    #pragma unroll
    for (int c = 0; c < CCH; c++) v[c] = __ldg(xp + (size_t)c * HW);
    float m = v[0];
    #pragma unroll
    for (int c = 1; c < CCH; c++) m = fmaxf(m, v[c]);
    float se = 0.0f, xt = v[0];
    #pragma unroll
    for (int c = 0; c < CCH; c++) {
        se += __expf(v[c] - m);
        if (c == t) xt = v[c];
    }
    return (t == 255) ? 0.0f : (m - xt + __logf(se));
}

// ---------------------------------------------------------------------------
__global__ __launch_bounds__(BLK) void ce_k(const float* __restrict__ x,
                                            const int* __restrict__ tgt,
                                            float* __restrict__ out) {
    const int p = blockIdx.x * BLK + threadIdx.x;   // exact grid: BHW/BLK
    const float loss = pixel_loss(x, p, __ldg(tgt + p));

    // Thresholded count/sum block reduction.
    const bool   gt = loss > THRESH;
    float        sv = gt ? loss : 0.0f;
    unsigned int cv = gt ? 1u : 0u;
    #pragma unroll
    for (int o = 16; o > 0; o >>= 1) {
        sv += __shfl_down_sync(0xffffffffu, sv, o);
        cv += __shfl_down_sync(0xffffffffu, cv, o);
    }
    __shared__ float    ss[8];
    __shared__ unsigned sc[8];
    const int lane = threadIdx.x & 31, w = threadIdx.x >> 5;
    if (lane == 0) { ss[w] = sv; sc[w] = cv; }
    __syncthreads();
    __shared__ bool isLast;
    if (threadIdx.x == 0) {
        float    s2 = 0.0f; unsigned c2 = 0u;
        #pragma unroll
        for (int i = 0; i < 8; i++) { s2 += ss[i]; c2 += sc[i]; }
        const int slot = blockIdx.x & (NPART - 1);
        atomicAdd(&g_part_sum[slot], (double)s2);
        atomicAdd(&g_part_cnt[slot], (unsigned long long)c2);
        // Release-ticket: orders this thread's prior global atomics without a
        // full gpu fence (no CCTL.IVALL / L1D invalidate). The winning add's
        // acquire half synchronizes with every earlier release in the
        // release sequence on g_ticket1, making all blocks' partials visible.
        unsigned ret;
        asm volatile("atom.acq_rel.gpu.global.add.u32 %0, [%1], %2;"
                     : "=r"(ret) : "l"(&g_ticket1), "r"(1u) : "memory");
        isLast = (ret == (unsigned)(gridDim.x - 1));
    }
    __syncthreads();
    if (!isLast) return;

    // ======================= LAST BLOCK ONLY ===============================
    const int tt = threadIdx.x;
    double             ds = (tt < NPART) ? g_part_sum[tt] : 0.0;
    unsigned long long dc = (tt < NPART) ? g_part_cnt[tt] : 0ull;
    if (tt < NPART) { g_part_sum[tt] = 0.0; g_part_cnt[tt] = 0ull; }  // self-reset

    __shared__ double             fs[BLK];
    __shared__ unsigned long long fc[BLK];
    fs[tt] = ds; fc[tt] = dc;
    __syncthreads();
    for (int o = BLK / 2; o > 0; o >>= 1) {
        if (tt < o) { fs[tt] += fs[tt + o]; fc[tt] += fc[tt + o]; }
        __syncthreads();
    }
    __shared__ int fastpath;
    if (tt == 0) {
        const double             S = fs[0];
        const unsigned long long C = fc[0];
        if (C > (unsigned long long)NMIN) { out[0] = (float)(S / (double)C); fastpath = 1; }
        else                              { fastpath = 0; }
        g_ticket1 = 0u;                          // self-reset for next replay
    }
    __syncthreads();
    if (fastpath) return;                        // <-- bench data exits here

    // ---- Fallback (top-NMIN mean). Single block, correctness-only path. ----
    for (int i = tt; i < NBINS; i += BLK) { g_hist_cnt[i] = 0u; g_hist_sum[i] = 0.0f; }
    __syncthreads();
    for (int q = tt; q < BHW; q += BLK) {
        const float l = pixel_loss(x, q, __ldg(tgt + q));
        unsigned bin = __float_as_uint(l) >> 16;     // monotone for l >= 0
        if (bin >= NBINS) bin = NBINS - 1;
        atomicAdd(&g_hist_cnt[bin], 1u);
        atomicAdd(&g_hist_sum[bin], l);
    }
    __syncthreads();

    // Top-NMIN select over the histogram.
    __shared__ unsigned long long scnt[BLK];
    __shared__ double             ssum[BLK];
    {
        unsigned long long c = 0ull; double s = 0.0;
        for (int j = 0; j < NBINS / BLK; j++) {
            const int bin = NBINS - 1 - (tt * (NBINS / BLK) + j);
            c += g_hist_cnt[bin];
            s += (double)g_hist_sum[bin];
        }
        scnt[tt] = c; ssum[tt] = s;
    }
    __syncthreads();
    if (tt == 0) {
        unsigned long long cum = 0ull; double sum = 0.0;
        int chunk = 0;
        for (chunk = 0; chunk < BLK; chunk++) {
            if (cum + scnt[chunk] >= (unsigned long long)NMIN) break;
            cum += scnt[chunk]; sum += ssum[chunk];
        }
        double result;
        if (chunk == BLK) {
            result = (cum > 0) ? (sum / (double)cum) : 0.0;
        } else {
            for (int j = 0; j < NBINS / BLK; j++) {
                const int bin = NBINS - 1 - (chunk * (NBINS / BLK) + j);
                const unsigned long long bc = g_hist_cnt[bin];
                const double             bs = (double)g_hist_sum[bin];
                if (cum + bc >= (unsigned long long)NMIN) {
                    const unsigned long long rem = (unsigned long long)NMIN - cum;
                    sum += (bc ? bs / (double)bc : 0.0) * (double)rem;
                    break;
                }
                cum += bc; sum += bs;
            }
            result = sum / (double)NMIN;
        }
        out[0] = (float)result;
    }
}

// ---------------------------------------------------------------------------
extern "C" void kernel_launch(void* const* d_in, const int* in_sizes, int n_in,
                              void* d_out, int out_size) {
    const float* x;
    const int*   tg;
    if (in_sizes[0] >= in_sizes[1]) { x = (const float*)d_in[0]; tg = (const int*)d_in[1]; }
    else                            { x = (const float*)d_in[1]; tg = (const int*)d_in[0]; }

    ce_k<<<CE_BLOCKS, BLK>>>(x, tg, (float*)d_out);
}